// round 2
// baseline (speedup 1.0000x reference)
#include <cuda_runtime.h>
#include <cuda_bf16.h>
#include <math.h>

// Problem constants
#define BATCH   2
#define NTXT    2048
#define T_MEDIA 4
#define M_MEDIA 256
#define TM_TOT  1024          // T_MEDIA * M_MEDIA
#define DIM     1024
#define HEADS   16
#define DH      64
#define EPS     1e-5f

// ---------------------------------------------------------------------------
// Scratch (device globals; no allocations allowed)
// ---------------------------------------------------------------------------
__device__ float g_tn  [BATCH * NTXT * DIM];      // LayerNorm(text)
__device__ float g_q   [BATCH * NTXT * DIM];      // q projection
__device__ float g_kv  [BATCH * TM_TOT * 2 * DIM];// k (cols 0..1023) | v (cols 1024..2047)
__device__ float g_attn[BATCH * NTXT * DIM];      // attention output (pre-Wo)
__device__ float g_vpart[BATCH * 16 * DIM];       // partial v sums
__device__ float g_vmean[BATCH * DIM];            // mean of v over all tm
__device__ int   g_tt  [BATCH * NTXT];            // txt_time = cumsum(locations)

// ---------------------------------------------------------------------------
// Inclusive scan of locations -> txt_time.  One block of 1024 per batch.
// ---------------------------------------------------------------------------
__global__ void scan_kernel(const int* __restrict__ loc) {
    int b = blockIdx.x;
    int tid = threadIdx.x;                       // 0..1023
    __shared__ int s[1024];
    const int* L = loc + b * NTXT;
    int a0 = L[2 * tid];
    int a1 = L[2 * tid + 1];
    int v0 = a0;
    int v1 = a0 + a1;
    s[tid] = v1;
    __syncthreads();
    for (int off = 1; off < 1024; off <<= 1) {
        int t = (tid >= off) ? s[tid - off] : 0;
        __syncthreads();
        s[tid] += t;
        __syncthreads();
    }
    int excl = s[tid] - v1;
    g_tt[b * NTXT + 2 * tid]     = excl + v0;
    g_tt[b * NTXT + 2 * tid + 1] = excl + v1;
}

// ---------------------------------------------------------------------------
// Block reduce helper (256 threads)
// ---------------------------------------------------------------------------
__device__ __forceinline__ float blockReduceSum256(float v, float* red) {
    #pragma unroll
    for (int o = 16; o; o >>= 1) v += __shfl_xor_sync(0xffffffffu, v, o);
    int lane = threadIdx.x & 31, w = threadIdx.x >> 5;
    if (lane == 0) red[w] = v;
    __syncthreads();
    float r = (threadIdx.x < 8) ? red[threadIdx.x] : 0.0f;
    if (threadIdx.x < 32) {
        #pragma unroll
        for (int o = 4; o; o >>= 1) r += __shfl_xor_sync(0xffffffffu, r, o);
        if (threadIdx.x == 0) red[0] = r;
    }
    __syncthreads();
    float out = red[0];
    __syncthreads();
    return out;
}

// ---------------------------------------------------------------------------
// LayerNorm: one block (256 thr) per row, 4 floats per thread via float4
// ---------------------------------------------------------------------------
__global__ void ln_kernel(const float* __restrict__ text,
                          const float* __restrict__ gamma,
                          const float* __restrict__ beta) {
    int row = blockIdx.x;                       // 0..4095
    const float4* x = (const float4*)(text + (size_t)row * DIM);
    float4* y = (float4*)(g_tn + (size_t)row * DIM);
    int tid = threadIdx.x;
    __shared__ float red[8];

    float4 v = x[tid];
    float s = v.x + v.y + v.z + v.w;
    float mu = blockReduceSum256(s, red) * (1.0f / DIM);
    float dx = v.x - mu, dy = v.y - mu, dz = v.z - mu, dw = v.w - mu;
    float ss = dx * dx + dy * dy + dz * dz + dw * dw;
    float var = blockReduceSum256(ss, red) * (1.0f / DIM);
    float inv = rsqrtf(var + EPS);
    float4 g = ((const float4*)gamma)[tid];
    float4 bt = ((const float4*)beta)[tid];
    float4 o;
    o.x = dx * inv * g.x + bt.x;
    o.y = dy * inv * g.y + bt.y;
    o.z = dz * inv * g.z + bt.z;
    o.w = dw * inv * g.w + bt.w;
    y[tid] = o;
}

// ---------------------------------------------------------------------------
// Tiled FP32 SGEMM: C[M,N] = A[M,K] @ B[K,N], all row-major.
// BM=BN=64, BK=16, 256 threads, 4x4 per thread. M%64==0, N%64==0, K%16==0.
// ---------------------------------------------------------------------------
#define BM 64
#define BN 64
#define BK 16
__global__ __launch_bounds__(256)
void sgemm64(const float* __restrict__ A, const float* __restrict__ B,
             float* __restrict__ C, int M, int N, int K) {
    __shared__ float As[BK][BM];
    __shared__ float Bs[BK][BN];
    int tid = threadIdx.x;
    int tx = tid & 15, ty = tid >> 4;
    int row0 = blockIdx.y * BM, col0 = blockIdx.x * BN;

    int a_r = tid >> 2;            // 0..63
    int a_k = (tid & 3) << 2;      // 0,4,8,12
    int b_r = tid >> 4;            // 0..15
    int b_c = (tid & 15) << 2;     // 0..60

    const float* Aptr = A + (size_t)(row0 + a_r) * K + a_k;
    const float* Bptr = B + (size_t)b_r * N + col0 + b_c;

    float acc[4][4];
    #pragma unroll
    for (int i = 0; i < 4; i++)
        #pragma unroll
        for (int j = 0; j < 4; j++) acc[i][j] = 0.0f;

    for (int k0 = 0; k0 < K; k0 += BK) {
        float4 av = *(const float4*)(Aptr + k0);
        As[a_k + 0][a_r] = av.x;
        As[a_k + 1][a_r] = av.y;
        As[a_k + 2][a_r] = av.z;
        As[a_k + 3][a_r] = av.w;
        *(float4*)&Bs[b_r][b_c] = *(const float4*)(Bptr + (size_t)k0 * N);
        __syncthreads();
        #pragma unroll
        for (int kk = 0; kk < BK; kk++) {
            float4 a4 = *(const float4*)&As[kk][ty << 2];
            float4 b4 = *(const float4*)&Bs[kk][tx << 2];
            float ar[4] = {a4.x, a4.y, a4.z, a4.w};
            float br[4] = {b4.x, b4.y, b4.z, b4.w};
            #pragma unroll
            for (int i = 0; i < 4; i++)
                #pragma unroll
                for (int j = 0; j < 4; j++)
                    acc[i][j] = fmaf(ar[i], br[j], acc[i][j]);
        }
        __syncthreads();
    }
    #pragma unroll
    for (int i = 0; i < 4; i++) {
        float4 o = make_float4(acc[i][0], acc[i][1], acc[i][2], acc[i][3]);
        *(float4*)&C[(size_t)(row0 + (ty << 2) + i) * N + col0 + (tx << 2)] = o;
    }
}

// ---------------------------------------------------------------------------
// v column partial sums + final mean (v lives in g_kv cols [1024, 2048))
// ---------------------------------------------------------------------------
__global__ void vpart_kernel() {
    int c  = blockIdx.x * 256 + threadIdx.x;    // 0..1023
    int ry = blockIdx.y;                        // 0..15 (64 rows each)
    int b  = blockIdx.z;
    const float* base = g_kv + ((size_t)(b * TM_TOT + ry * 64)) * (2 * DIM) + DIM + c;
    float s = 0.0f;
    #pragma unroll 8
    for (int j = 0; j < 64; j++) s += base[(size_t)j * (2 * DIM)];
    g_vpart[(b * 16 + ry) * DIM + c] = s;
}

__global__ void vmean_kernel() {
    int c = blockIdx.x * 256 + threadIdx.x;
    int b = blockIdx.y;
    float s = 0.0f;
    #pragma unroll
    for (int r = 0; r < 16; r++) s += g_vpart[(b * 16 + r) * DIM + c];
    g_vmean[b * DIM + c] = s * (1.0f / TM_TOT);
}

// ---------------------------------------------------------------------------
// Attention dispatch: one block (256 thr) per (b, query i).
//  tt == 0        -> zero row
//  tt in [1..4]   -> softmax attention over the 256-key media segment
//  tt > 4         -> uniform attention = vmean broadcast (exact)
// ---------------------------------------------------------------------------
__global__ __launch_bounds__(256)
void attn_kernel() {
    int bi = blockIdx.x;                        // 0..4095
    int b = bi >> 11;
    int i = bi & (NTXT - 1);
    int tid = threadIdx.x;
    int tt = g_tt[b * NTXT + i];
    float* orow = g_attn + (size_t)bi * DIM;

    if (tt == 0) {
        #pragma unroll
        for (int r = 0; r < 4; r++) orow[tid + 256 * r] = 0.0f;
        return;
    }
    if (tt > T_MEDIA) {
        const float* vm = g_vmean + b * DIM;
        #pragma unroll
        for (int r = 0; r < 4; r++) orow[tid + 256 * r] = vm[tid + 256 * r];
        return;
    }

    // segment attention
    __shared__ float qs[DIM];
    __shared__ float S[HEADS * M_MEDIA];        // 16KB
    int j0 = (tt - 1) * M_MEDIA;
    ((float4*)qs)[tid] = ((const float4*)(g_q + (size_t)bi * DIM))[tid];
    __syncthreads();

    const float scale = 0.125f;                 // DH^-0.5
    int h = tid >> 4, jj = tid & 15;
    #pragma unroll 2
    for (int jb = 0; jb < 16; jb++) {
        int j = jj * 16 + jb;
        const float* krow = g_kv + ((size_t)(b * TM_TOT + j0 + j)) * (2 * DIM) + h * DH;
        const float* qh = qs + h * DH;
        float s = 0.0f;
        #pragma unroll
        for (int d = 0; d < DH; d += 4) {
            float4 k4 = *(const float4*)(krow + d);
            float4 q4 = *(const float4*)(qh + d);
            s += q4.x * k4.x + q4.y * k4.y + q4.z * k4.z + q4.w * k4.w;
        }
        S[h * M_MEDIA + j] = s * scale;
    }
    __syncthreads();

    // softmax per head; warp w handles heads 2w and 2w+1
    int w = tid >> 5, lane = tid & 31;
    for (int hh = 2 * w; hh < 2 * w + 2; hh++) {
        float vals[8];
        float m = -1e30f;
        #pragma unroll
        for (int k = 0; k < 8; k++) {
            vals[k] = S[hh * M_MEDIA + lane + 32 * k];
            m = fmaxf(m, vals[k]);
        }
        #pragma unroll
        for (int o = 16; o; o >>= 1) m = fmaxf(m, __shfl_xor_sync(0xffffffffu, m, o));
        float sum = 0.0f;
        #pragma unroll
        for (int k = 0; k < 8; k++) {
            vals[k] = __expf(vals[k] - m);
            sum += vals[k];
        }
        #pragma unroll
        for (int o = 16; o; o >>= 1) sum += __shfl_xor_sync(0xffffffffu, sum, o);
        float inv = 1.0f / sum;
        #pragma unroll
        for (int k = 0; k < 8; k++) S[hh * M_MEDIA + lane + 32 * k] = vals[k] * inv;
    }
    __syncthreads();

    // out[c] = sum_j p[c/64][j] * v[j0+j][c];  thread owns cols tid + 256*r
    float acc[4] = {0.f, 0.f, 0.f, 0.f};
    const float* vbase = g_kv + ((size_t)(b * TM_TOT + j0)) * (2 * DIM) + DIM;
    #pragma unroll 4
    for (int j = 0; j < M_MEDIA; j++) {
        const float* vr = vbase + (size_t)j * (2 * DIM);
        #pragma unroll
        for (int r = 0; r < 4; r++) {
            int c = tid + 256 * r;
            acc[r] = fmaf(S[(c >> 6) * M_MEDIA + j], vr[c], acc[r]);
        }
    }
    #pragma unroll
    for (int r = 0; r < 4; r++) orow[tid + 256 * r] = acc[r];
}

// ---------------------------------------------------------------------------
// Launch
// ---------------------------------------------------------------------------
extern "C" void kernel_launch(void* const* d_in, const int* in_sizes, int n_in,
                              void* d_out, int out_size) {
    const float* text  = (const float*)d_in[0];
    const float* image = (const float*)d_in[1];
    const int*   loc   = (const int*)d_in[2];
    const float* Wq    = (const float*)d_in[3];
    const float* Wkv   = (const float*)d_in[4];
    const float* Wo    = (const float*)d_in[5];
    const float* gamma = (const float*)d_in[6];
    const float* beta  = (const float*)d_in[7];
    float* out = (float*)d_out;

    float *p_tn, *p_q, *p_kv, *p_attn;
    cudaGetSymbolAddress((void**)&p_tn,   g_tn);
    cudaGetSymbolAddress((void**)&p_q,    g_q);
    cudaGetSymbolAddress((void**)&p_kv,   g_kv);
    cudaGetSymbolAddress((void**)&p_attn, g_attn);

    // txt_time scan + LayerNorm (independent)
    scan_kernel<<<BATCH, 1024>>>(loc);
    ln_kernel<<<BATCH * NTXT, 256>>>(text, gamma, beta);

    // kv = image @ Wkv   (2048 x 2048 x 1024)
    sgemm64<<<dim3(2 * DIM / BN, BATCH * TM_TOT / BM), 256>>>(
        image, Wkv, p_kv, BATCH * TM_TOT, 2 * DIM, DIM);

    // vmean (needs kv)
    vpart_kernel<<<dim3(DIM / 256, 16, BATCH), 256>>>();
    vmean_kernel<<<dim3(DIM / 256, BATCH), 256>>>();

    // q = tn @ Wq   (4096 x 1024 x 1024)
    sgemm64<<<dim3(DIM / BN, BATCH * NTXT / BM), 256>>>(
        p_tn, Wq, p_q, BATCH * NTXT, DIM, DIM);

    // attention dispatch
    attn_kernel<<<BATCH * NTXT, 256>>>();

    // out = attn @ Wo   (4096 x 1024 x 1024)
    sgemm64<<<dim3(DIM / BN, BATCH * NTXT / BM), 256>>>(
        p_attn, Wo, out, BATCH * NTXT, DIM, DIM);
}

// round 4
// speedup vs baseline: 2.4410x; 2.4410x over previous
#include <cuda_runtime.h>
#include <cuda_bf16.h>
#include <math.h>
#include <stdint.h>

// Problem constants
#define BATCH   2
#define NTXT    2048
#define T_MEDIA 4
#define M_MEDIA 256
#define TM_TOT  1024
#define DIM     1024
#define HEADS   16
#define DH      64
#define EPS     1e-5f

#define MQ  (BATCH * NTXT)     // 4096
#define MKV (BATCH * TM_TOT)   // 2048

// ---------------------------------------------------------------------------
// Scratch (device globals; no allocations allowed)
// ---------------------------------------------------------------------------
__device__ __nv_bfloat16 g_tn_hi [MQ * DIM];
__device__ __nv_bfloat16 g_tn_lo [MQ * DIM];
__device__ __nv_bfloat16 g_img_hi[MKV * DIM];
__device__ __nv_bfloat16 g_img_lo[MKV * DIM];
__device__ __nv_bfloat16 g_at_hi [MQ * DIM];
__device__ __nv_bfloat16 g_at_lo [MQ * DIM];
__device__ __nv_bfloat16 g_Wq_hi [DIM * DIM];      // [N,K] transposed
__device__ __nv_bfloat16 g_Wq_lo [DIM * DIM];
__device__ __nv_bfloat16 g_Wkv_hi[2 * DIM * DIM];
__device__ __nv_bfloat16 g_Wkv_lo[2 * DIM * DIM];
__device__ __nv_bfloat16 g_Wo_hi [DIM * DIM];
__device__ __nv_bfloat16 g_Wo_lo [DIM * DIM];

__device__ float g_q   [MQ * DIM];
__device__ float g_kv  [MKV * 2 * DIM];            // k | v
__device__ float g_vpart[BATCH * 16 * DIM];
__device__ float g_vmean[BATCH * DIM];
__device__ int   g_tt  [BATCH * NTXT];

// ---------------------------------------------------------------------------
// PTX helpers (sm_80-baseline only; NO tcgen05 — ptxas target lacks 'a')
// ---------------------------------------------------------------------------
__device__ __forceinline__ uint32_t smem_u32(const void* p) {
    uint32_t a;
    asm("{ .reg .u64 t; cvta.to.shared.u64 t, %1; cvt.u32.u64 %0, t; }" : "=r"(a) : "l"(p));
    return a;
}
__device__ __forceinline__ void cp_async16(uint32_t dst, const void* src) {
    asm volatile("cp.async.cg.shared.global [%0], [%1], 16;\n" :: "r"(dst), "l"(src));
}
__device__ __forceinline__ void ldsm4(uint32_t* r, uint32_t addr) {
    asm volatile("ldmatrix.sync.aligned.m8n8.x4.shared.b16 {%0,%1,%2,%3}, [%4];"
                 : "=r"(r[0]), "=r"(r[1]), "=r"(r[2]), "=r"(r[3]) : "r"(addr));
}
__device__ __forceinline__ void mma16816(float* c, const uint32_t* a,
                                         uint32_t b0, uint32_t b1) {
    asm volatile(
        "mma.sync.aligned.m16n8k16.row.col.f32.bf16.bf16.f32 "
        "{%0,%1,%2,%3}, {%4,%5,%6,%7}, {%8,%9}, {%0,%1,%2,%3};"
        : "+f"(c[0]), "+f"(c[1]), "+f"(c[2]), "+f"(c[3])
        : "r"(a[0]), "r"(a[1]), "r"(a[2]), "r"(a[3]), "r"(b0), "r"(b1));
}
__device__ __forceinline__ uint32_t sw128(uint32_t off) {
    return off ^ ((off >> 3) & 0x70);
}
__device__ __forceinline__ void split2(float v, __nv_bfloat16& h, __nv_bfloat16& l) {
    h = __float2bfloat16(v);
    l = __float2bfloat16(v - __bfloat162float(h));
}

// ---------------------------------------------------------------------------
// Inclusive scan of locations -> txt_time.  One block of 1024 per batch.
// ---------------------------------------------------------------------------
__global__ void scan_kernel(const int* __restrict__ loc) {
    int b = blockIdx.x;
    int tid = threadIdx.x;
    __shared__ int s[1024];
    const int* L = loc + b * NTXT;
    int a0 = L[2 * tid];
    int a1 = L[2 * tid + 1];
    int v0 = a0, v1 = a0 + a1;
    s[tid] = v1;
    __syncthreads();
    for (int off = 1; off < 1024; off <<= 1) {
        int t = (tid >= off) ? s[tid - off] : 0;
        __syncthreads();
        s[tid] += t;
        __syncthreads();
    }
    int excl = s[tid] - v1;
    g_tt[b * NTXT + 2 * tid]     = excl + v0;
    g_tt[b * NTXT + 2 * tid + 1] = excl + v1;
}

// ---------------------------------------------------------------------------
// Block reduce helper (256 threads)
// ---------------------------------------------------------------------------
__device__ __forceinline__ float blockReduceSum256(float v, float* red) {
    #pragma unroll
    for (int o = 16; o; o >>= 1) v += __shfl_xor_sync(0xffffffffu, v, o);
    int lane = threadIdx.x & 31, w = threadIdx.x >> 5;
    if (lane == 0) red[w] = v;
    __syncthreads();
    float r = (threadIdx.x < 8) ? red[threadIdx.x] : 0.0f;
    if (threadIdx.x < 32) {
        #pragma unroll
        for (int o = 4; o; o >>= 1) r += __shfl_xor_sync(0xffffffffu, r, o);
        if (threadIdx.x == 0) red[0] = r;
    }
    __syncthreads();
    float out = red[0];
    __syncthreads();
    return out;
}

// ---------------------------------------------------------------------------
// LayerNorm -> hi/lo bf16
// ---------------------------------------------------------------------------
__global__ void ln_kernel(const float* __restrict__ text,
                          const float* __restrict__ gamma,
                          const float* __restrict__ beta) {
    int row = blockIdx.x;
    const float4* x = (const float4*)(text + (size_t)row * DIM);
    int tid = threadIdx.x;
    __shared__ float red[8];

    float4 v = x[tid];
    float s = v.x + v.y + v.z + v.w;
    float mu = blockReduceSum256(s, red) * (1.0f / DIM);
    float dx = v.x - mu, dy = v.y - mu, dz = v.z - mu, dw = v.w - mu;
    float ss = dx * dx + dy * dy + dz * dz + dw * dw;
    float var = blockReduceSum256(ss, red) * (1.0f / DIM);
    float inv = rsqrtf(var + EPS);
    float4 g = ((const float4*)gamma)[tid];
    float4 bt = ((const float4*)beta)[tid];
    float o[4];
    o[0] = dx * inv * g.x + bt.x;
    o[1] = dy * inv * g.y + bt.y;
    o[2] = dz * inv * g.z + bt.z;
    o[3] = dw * inv * g.w + bt.w;
    __nv_bfloat16 h[4], l[4];
    #pragma unroll
    for (int i = 0; i < 4; i++) split2(o[i], h[i], l[i]);
    size_t base = (size_t)row * DIM + 4 * tid;
    *(__nv_bfloat162*)(g_tn_hi + base)     = __nv_bfloat162(h[0], h[1]);
    *(__nv_bfloat162*)(g_tn_hi + base + 2) = __nv_bfloat162(h[2], h[3]);
    *(__nv_bfloat162*)(g_tn_lo + base)     = __nv_bfloat162(l[0], l[1]);
    *(__nv_bfloat162*)(g_tn_lo + base + 2) = __nv_bfloat162(l[2], l[3]);
}

// ---------------------------------------------------------------------------
// image fp32 -> hi/lo bf16 (elementwise)
// ---------------------------------------------------------------------------
__global__ void conv_img(const float* __restrict__ img) {
    size_t i = ((size_t)blockIdx.x * 256 + threadIdx.x) * 4;
    float4 v = *(const float4*)(img + i);
    __nv_bfloat16 h[4], l[4];
    split2(v.x, h[0], l[0]); split2(v.y, h[1], l[1]);
    split2(v.z, h[2], l[2]); split2(v.w, h[3], l[3]);
    *(__nv_bfloat162*)(g_img_hi + i)     = __nv_bfloat162(h[0], h[1]);
    *(__nv_bfloat162*)(g_img_hi + i + 2) = __nv_bfloat162(h[2], h[3]);
    *(__nv_bfloat162*)(g_img_lo + i)     = __nv_bfloat162(l[0], l[1]);
    *(__nv_bfloat162*)(g_img_lo + i + 2) = __nv_bfloat162(l[2], l[3]);
}

// ---------------------------------------------------------------------------
// W [K,N] fp32 -> W^T [N,K] hi/lo bf16 (tiled transpose)
// ---------------------------------------------------------------------------
__global__ void wtrans(const float* __restrict__ W,
                       __nv_bfloat16* __restrict__ Thi,
                       __nv_bfloat16* __restrict__ Tlo,
                       int Kd, int Nd) {
    __shared__ float t[32][33];
    int bx = blockIdx.x * 32;  // N offset
    int by = blockIdx.y * 32;  // K offset
    int x = threadIdx.x & 31, y4 = (threadIdx.x >> 5) * 4;
    #pragma unroll
    for (int i = 0; i < 4; i++)
        t[y4 + i][x] = W[(size_t)(by + y4 + i) * Nd + bx + x];
    __syncthreads();
    #pragma unroll
    for (int i = 0; i < 4; i++) {
        float v = t[x][y4 + i];
        __nv_bfloat16 h, l;
        split2(v, h, l);
        size_t o = (size_t)(bx + y4 + i) * Kd + by + x;
        Thi[o] = h;
        Tlo[o] = l;
    }
}

// ---------------------------------------------------------------------------
// bf16 split GEMM via mma.sync (HMMA):  C[M,N] = A[M,K] @ B^T  (B stored [N,K])
// Effective K' = 3K via [A_hi|A_hi|A_lo] . [B_hi|B_lo|B_hi]
// Tile 128x128, BK=64, 256 thr (8 warps, each 64x32), cp.async double buffer.
// ---------------------------------------------------------------------------
#define GBM 128
#define GBN 128
#define GBK 64
#define KTILES 48                     // 3*1024/64
#define ABYTES (GBM * GBK * 2)        // 16384
#define BBYTES (GBN * GBK * 2)        // 16384
#define SMEM_GEMM (2 * (ABYTES + BBYTES))   // 65536

__global__ __launch_bounds__(256, 2)
void gemm_hmma_split(const __nv_bfloat16* __restrict__ A_hi,
                     const __nv_bfloat16* __restrict__ A_lo,
                     const __nv_bfloat16* __restrict__ B_hi,
                     const __nv_bfloat16* __restrict__ B_lo,
                     float* __restrict__ C, int N) {
    extern __shared__ char smem[];
    const int K = 1024;
    uint32_t sb = smem_u32(smem);
    int tid = threadIdx.x;
    int lane = tid & 31, wid = tid >> 5;
    int row0 = blockIdx.y * GBM, col0 = blockIdx.x * GBN;

    const uint32_t aoff[2] = {0u, (uint32_t)(ABYTES + BBYTES)};
    const uint32_t boff[2] = {(uint32_t)ABYTES, (uint32_t)(2 * ABYTES + BBYTES)};

    // loader indices: 1024 16B-chunks per tile, 4 per thread
    int lr = tid >> 3;            // 0..31
    int lc = tid & 7;             // 0..7 (16B chunk within 128B row)

    // compute indices
    int wm = wid >> 2, wn = wid & 3;
    int m_warp = wm * 64, n_warp = wn * 32;
    int a_row = lane & 15;
    int a_colb = (lane >> 4) * 8;            // k offset 0/8
    int b_row = (lane & 7) + 8 * ((lane >> 4) & 1);
    int b_colb = 8 * ((lane >> 3) & 1);

    float acc[4][4][4];
    #pragma unroll
    for (int i = 0; i < 4; i++)
        #pragma unroll
        for (int j = 0; j < 4; j++)
            #pragma unroll
            for (int q = 0; q < 4; q++) acc[i][j][q] = 0.0f;

    // ---- async load of one (A,B) k-chunk into buffer ----
    auto issue = [&](int kt) {
        int term = kt >> 4;
        int ks = (kt & 15) * GBK;
        int buf = kt & 1;
        const __nv_bfloat16* Ag = (term < 2) ? A_hi : A_lo;
        const __nv_bfloat16* Bg = (term == 1) ? B_lo : B_hi;
        #pragma unroll
        for (int j = 0; j < 4; j++) {
            int r = lr + 32 * j;
            uint32_t off = (uint32_t)(r * 128 + lc * 16);
            cp_async16(sb + aoff[buf] + sw128(off),
                       Ag + (size_t)(row0 + r) * K + ks + lc * 8);
        }
        #pragma unroll
        for (int j = 0; j < 4; j++) {
            int r = lr + 32 * j;
            uint32_t off = (uint32_t)(r * 128 + lc * 16);
            cp_async16(sb + boff[buf] + sw128(off),
                       Bg + (size_t)(col0 + r) * K + ks + lc * 8);
        }
        asm volatile("cp.async.commit_group;" ::: "memory");
    };

    issue(0);

    #pragma unroll 1
    for (int kt = 0; kt < KTILES; kt++) {
        int buf = kt & 1;
        if (kt + 1 < KTILES) {
            issue(kt + 1);
            asm volatile("cp.async.wait_group 1;" ::: "memory");
        } else {
            asm volatile("cp.async.wait_group 0;" ::: "memory");
        }
        __syncthreads();

        uint32_t ab = sb + aoff[buf], bb = sb + boff[buf];
        #pragma unroll
        for (int k16 = 0; k16 < 4; k16++) {
            uint32_t a_r[4][4], b_r[2][4];
            #pragma unroll
            for (int mf = 0; mf < 4; mf++) {
                uint32_t off = (uint32_t)((m_warp + mf * 16 + a_row) * 128 +
                                          (k16 * 16 + a_colb) * 2);
                ldsm4(a_r[mf], ab + sw128(off));
            }
            #pragma unroll
            for (int nf2 = 0; nf2 < 2; nf2++) {
                uint32_t off = (uint32_t)((n_warp + nf2 * 16 + b_row) * 128 +
                                          (k16 * 16 + b_colb) * 2);
                ldsm4(b_r[nf2], bb + sw128(off));
            }
            #pragma unroll
            for (int mf = 0; mf < 4; mf++)
                #pragma unroll
                for (int nf = 0; nf < 4; nf++) {
                    const uint32_t* b2 = &b_r[nf >> 1][(nf & 1) * 2];
                    mma16816(acc[mf][nf], a_r[mf], b2[0], b2[1]);
                }
        }
        __syncthreads();
    }

    // ---- epilogue ----
    int r_base = row0 + m_warp + (lane >> 2);
    int c_base = col0 + n_warp + 2 * (lane & 3);
    #pragma unroll
    for (int mf = 0; mf < 4; mf++)
        #pragma unroll
        for (int nf = 0; nf < 4; nf++) {
            float* p = C + (size_t)(r_base + mf * 16) * N + c_base + nf * 8;
            *(float2*)p = make_float2(acc[mf][nf][0], acc[mf][nf][1]);
            *(float2*)(p + (size_t)8 * N) = make_float2(acc[mf][nf][2], acc[mf][nf][3]);
        }
}

// ---------------------------------------------------------------------------
// v column partial sums + final mean
// ---------------------------------------------------------------------------
__global__ void vpart_kernel() {
    int c  = blockIdx.x * 256 + threadIdx.x;
    int ry = blockIdx.y;
    int b  = blockIdx.z;
    const float* base = g_kv + ((size_t)(b * TM_TOT + ry * 64)) * (2 * DIM) + DIM + c;
    float s = 0.0f;
    #pragma unroll 8
    for (int j = 0; j < 64; j++) s += base[(size_t)j * (2 * DIM)];
    g_vpart[(b * 16 + ry) * DIM + c] = s;
}

__global__ void vmean_kernel() {
    int c = blockIdx.x * 256 + threadIdx.x;
    int b = blockIdx.y;
    float s = 0.0f;
    #pragma unroll
    for (int r = 0; r < 16; r++) s += g_vpart[(b * 16 + r) * DIM + c];
    g_vmean[b * DIM + c] = s * (1.0f / TM_TOT);
}

// ---------------------------------------------------------------------------
// Attention dispatch -> writes hi/lo bf16 rows (A of the Wo GEMM)
// ---------------------------------------------------------------------------
__global__ __launch_bounds__(256)
void attn_kernel() {
    int bi = blockIdx.x;
    int b = bi >> 11;
    int i = bi & (NTXT - 1);
    int tid = threadIdx.x;
    int tt = g_tt[b * NTXT + i];
    __nv_bfloat16* oh = g_at_hi + (size_t)bi * DIM;
    __nv_bfloat16* ol = g_at_lo + (size_t)bi * DIM;

    if (tt == 0) {
        __nv_bfloat16 z = __float2bfloat16(0.0f);
        #pragma unroll
        for (int r = 0; r < 4; r++) { oh[tid + 256 * r] = z; ol[tid + 256 * r] = z; }
        return;
    }
    if (tt > T_MEDIA) {
        const float* vm = g_vmean + b * DIM;
        #pragma unroll
        for (int r = 0; r < 4; r++) {
            __nv_bfloat16 h, l;
            split2(vm[tid + 256 * r], h, l);
            oh[tid + 256 * r] = h; ol[tid + 256 * r] = l;
        }
        return;
    }

    __shared__ float qs[DIM];
    __shared__ float S[HEADS * M_MEDIA];
    int j0 = (tt - 1) * M_MEDIA;
    ((float4*)qs)[tid] = ((const float4*)(g_q + (size_t)bi * DIM))[tid];
    __syncthreads();

    const float scale = 0.125f;
    int h = tid >> 4, jj = tid & 15;
    #pragma unroll 2
    for (int jb = 0; jb < 16; jb++) {
        int j = jj * 16 + jb;
        const float* krow = g_kv + ((size_t)(b * TM_TOT + j0 + j)) * (2 * DIM) + h * DH;
        const float* qh = qs + h * DH;
        float s = 0.0f;
        #pragma unroll
        for (int d = 0; d < DH; d += 4) {
            float4 k4 = *(const float4*)(krow + d);
            float4 q4 = *(const float4*)(qh + d);
            s += q4.x * k4.x + q4.y * k4.y + q4.z * k4.z + q4.w * k4.w;
        }
        S[h * M_MEDIA + j] = s * scale;
    }
    __syncthreads();

    int w = tid >> 5, lane = tid & 31;
    for (int hh = 2 * w; hh < 2 * w + 2; hh++) {
        float vals[8];
        float m = -1e30f;
        #pragma unroll
        for (int k = 0; k < 8; k++) {
            vals[k] = S[hh * M_MEDIA + lane + 32 * k];
            m = fmaxf(m, vals[k]);
        }
        #pragma unroll
        for (int o = 16; o; o >>= 1) m = fmaxf(m, __shfl_xor_sync(0xffffffffu, m, o));
        float sum = 0.0f;
        #pragma unroll
        for (int k = 0; k < 8; k++) { vals[k] = __expf(vals[k] - m); sum += vals[k]; }
        #pragma unroll
        for (int o = 16; o; o >>= 1) sum += __shfl_xor_sync(0xffffffffu, sum, o);
        float inv = 1.0f / sum;
        #pragma unroll
        for (int k = 0; k < 8; k++) S[hh * M_MEDIA + lane + 32 * k] = vals[k] * inv;
    }
    __syncthreads();

    float acc[4] = {0.f, 0.f, 0.f, 0.f};
    const float* vbase = g_kv + ((size_t)(b * TM_TOT + j0)) * (2 * DIM) + DIM;
    #pragma unroll 4
    for (int j = 0; j < M_MEDIA; j++) {
        const float* vr = vbase + (size_t)j * (2 * DIM);
        #pragma unroll
        for (int r = 0; r < 4; r++) {
            int c = tid + 256 * r;
            acc[r] = fmaf(S[(c >> 6) * M_MEDIA + j], vr[c], acc[r]);
        }
    }
    #pragma unroll
    for (int r = 0; r < 4; r++) {
        __nv_bfloat16 hh, ll;
        split2(acc[r], hh, ll);
        oh[tid + 256 * r] = hh; ol[tid + 256 * r] = ll;
    }
}

// ---------------------------------------------------------------------------
// Launch
// ---------------------------------------------------------------------------
extern "C" void kernel_launch(void* const* d_in, const int* in_sizes, int n_in,
                              void* d_out, int out_size) {
    const float* text  = (const float*)d_in[0];
    const float* image = (const float*)d_in[1];
    const int*   loc   = (const int*)d_in[2];
    const float* Wq    = (const float*)d_in[3];
    const float* Wkv   = (const float*)d_in[4];
    const float* Wo    = (const float*)d_in[5];
    const float* gamma = (const float*)d_in[6];
    const float* beta  = (const float*)d_in[7];
    float* out = (float*)d_out;

    static int smem_set = 0;
    if (!smem_set) {
        cudaFuncSetAttribute(gemm_hmma_split,
                             cudaFuncAttributeMaxDynamicSharedMemorySize, SMEM_GEMM);
        smem_set = 1;
    }

    __nv_bfloat16 *tn_hi, *tn_lo, *img_hi, *img_lo, *at_hi, *at_lo;
    __nv_bfloat16 *wq_hi, *wq_lo, *wkv_hi, *wkv_lo, *wo_hi, *wo_lo;
    float *p_q, *p_kv;
    cudaGetSymbolAddress((void**)&tn_hi,  g_tn_hi);
    cudaGetSymbolAddress((void**)&tn_lo,  g_tn_lo);
    cudaGetSymbolAddress((void**)&img_hi, g_img_hi);
    cudaGetSymbolAddress((void**)&img_lo, g_img_lo);
    cudaGetSymbolAddress((void**)&at_hi,  g_at_hi);
    cudaGetSymbolAddress((void**)&at_lo,  g_at_lo);
    cudaGetSymbolAddress((void**)&wq_hi,  g_Wq_hi);
    cudaGetSymbolAddress((void**)&wq_lo,  g_Wq_lo);
    cudaGetSymbolAddress((void**)&wkv_hi, g_Wkv_hi);
    cudaGetSymbolAddress((void**)&wkv_lo, g_Wkv_lo);
    cudaGetSymbolAddress((void**)&wo_hi,  g_Wo_hi);
    cudaGetSymbolAddress((void**)&wo_lo,  g_Wo_lo);
    cudaGetSymbolAddress((void**)&p_q,    g_q);
    cudaGetSymbolAddress((void**)&p_kv,   g_kv);

    // scan + LN + conversions
    scan_kernel<<<BATCH, 1024>>>(loc);
    ln_kernel<<<MQ, 256>>>(text, gamma, beta);
    conv_img<<<(MKV * DIM) / (256 * 4), 256>>>(image);
    wtrans<<<dim3(2 * DIM / 32, DIM / 32), 256>>>(Wkv, wkv_hi, wkv_lo, DIM, 2 * DIM);
    wtrans<<<dim3(DIM / 32, DIM / 32), 256>>>(Wq, wq_hi, wq_lo, DIM, DIM);
    wtrans<<<dim3(DIM / 32, DIM / 32), 256>>>(Wo, wo_hi, wo_lo, DIM, DIM);

    // kv = image @ Wkv   (2048 x 2048)
    gemm_hmma_split<<<dim3(2 * DIM / GBN, MKV / GBM), 256, SMEM_GEMM>>>(
        img_hi, img_lo, wkv_hi, wkv_lo, p_kv, 2 * DIM);

    vpart_kernel<<<dim3(DIM / 256, 16, BATCH), 256>>>();
    vmean_kernel<<<dim3(DIM / 256, BATCH), 256>>>();

    // q = tn @ Wq        (4096 x 1024)
    gemm_hmma_split<<<dim3(DIM / GBN, MQ / GBM), 256, SMEM_GEMM>>>(
        tn_hi, tn_lo, wq_hi, wq_lo, p_q, DIM);

    attn_kernel<<<MQ, 256>>>();

    // out = attn @ Wo    (4096 x 1024)
    gemm_hmma_split<<<dim3(DIM / GBN, MQ / GBM), 256, SMEM_GEMM>>>(
        at_hi, at_lo, wo_hi, wo_lo, out, DIM);
}

// round 5
// speedup vs baseline: 2.6245x; 1.0752x over previous
#include <cuda_runtime.h>
#include <cuda_bf16.h>
#include <math.h>
#include <stdint.h>

// Problem constants
#define BATCH   2
#define NTXT    2048
#define T_MEDIA 4
#define M_MEDIA 256
#define TM_TOT  1024
#define DIM     1024
#define HEADS   16
#define DH      64
#define EPS     1e-5f

#define MQ  (BATCH * NTXT)     // 4096
#define MKV (BATCH * TM_TOT)   // 2048

// ---------------------------------------------------------------------------
// Scratch (device globals; no allocations allowed)
// ---------------------------------------------------------------------------
__device__ __nv_bfloat16 g_tn_hi [MQ * DIM];
__device__ __nv_bfloat16 g_tn_lo [MQ * DIM];
__device__ __nv_bfloat16 g_img_hi[MKV * DIM];
__device__ __nv_bfloat16 g_img_lo[MKV * DIM];
__device__ __nv_bfloat16 g_at_hi [MQ * DIM];
__device__ __nv_bfloat16 g_at_lo [MQ * DIM];
__device__ __nv_bfloat16 g_Wq_hi [DIM * DIM];      // [N,K] transposed
__device__ __nv_bfloat16 g_Wq_lo [DIM * DIM];
__device__ __nv_bfloat16 g_Wkv_hi[2 * DIM * DIM];
__device__ __nv_bfloat16 g_Wkv_lo[2 * DIM * DIM];
__device__ __nv_bfloat16 g_Wo_hi [DIM * DIM];
__device__ __nv_bfloat16 g_Wo_lo [DIM * DIM];

__device__ float g_q   [MQ * DIM];
__device__ float g_kv  [MKV * 2 * DIM];            // k | v
__device__ float g_vpart[BATCH * 32 * DIM];
__device__ float g_vmean[BATCH * DIM];
__device__ float g_omean[BATCH * DIM];             // vmean @ Wo (fp32)
__device__ int   g_tt  [BATCH * NTXT];

// ---------------------------------------------------------------------------
// PTX helpers (sm_80-baseline only; NO tcgen05 — ptxas target lacks 'a')
// ---------------------------------------------------------------------------
__device__ __forceinline__ uint32_t smem_u32(const void* p) {
    uint32_t a;
    asm("{ .reg .u64 t; cvta.to.shared.u64 t, %1; cvt.u32.u64 %0, t; }" : "=r"(a) : "l"(p));
    return a;
}
__device__ __forceinline__ void cp_async16(uint32_t dst, const void* src) {
    asm volatile("cp.async.cg.shared.global [%0], [%1], 16;\n" :: "r"(dst), "l"(src));
}
__device__ __forceinline__ void ldsm4(uint32_t* r, uint32_t addr) {
    asm volatile("ldmatrix.sync.aligned.m8n8.x4.shared.b16 {%0,%1,%2,%3}, [%4];"
                 : "=r"(r[0]), "=r"(r[1]), "=r"(r[2]), "=r"(r[3]) : "r"(addr));
}
__device__ __forceinline__ void mma16816(float* c, const uint32_t* a,
                                         uint32_t b0, uint32_t b1) {
    asm volatile(
        "mma.sync.aligned.m16n8k16.row.col.f32.bf16.bf16.f32 "
        "{%0,%1,%2,%3}, {%4,%5,%6,%7}, {%8,%9}, {%0,%1,%2,%3};"
        : "+f"(c[0]), "+f"(c[1]), "+f"(c[2]), "+f"(c[3])
        : "r"(a[0]), "r"(a[1]), "r"(a[2]), "r"(a[3]), "r"(b0), "r"(b1));
}
__device__ __forceinline__ uint32_t sw128(uint32_t off) {
    return off ^ ((off >> 3) & 0x70);
}
__device__ __forceinline__ void split2(float v, __nv_bfloat16& h, __nv_bfloat16& l) {
    h = __float2bfloat16(v);
    l = __float2bfloat16(v - __bfloat162float(h));
}

// ---------------------------------------------------------------------------
// Inclusive scan of locations -> txt_time.  One block of 1024 per batch.
// ---------------------------------------------------------------------------
__global__ void scan_kernel(const int* __restrict__ loc) {
    int b = blockIdx.x;
    int tid = threadIdx.x;
    __shared__ int s[1024];
    const int* L = loc + b * NTXT;
    int a0 = L[2 * tid];
    int a1 = L[2 * tid + 1];
    int v0 = a0, v1 = a0 + a1;
    s[tid] = v1;
    __syncthreads();
    for (int off = 1; off < 1024; off <<= 1) {
        int t = (tid >= off) ? s[tid - off] : 0;
        __syncthreads();
        s[tid] += t;
        __syncthreads();
    }
    int excl = s[tid] - v1;
    g_tt[b * NTXT + 2 * tid]     = excl + v0;
    g_tt[b * NTXT + 2 * tid + 1] = excl + v1;
}

// ---------------------------------------------------------------------------
// Block reduce helper (256 threads)
// ---------------------------------------------------------------------------
__device__ __forceinline__ float blockReduceSum256(float v, float* red) {
    #pragma unroll
    for (int o = 16; o; o >>= 1) v += __shfl_xor_sync(0xffffffffu, v, o);
    int lane = threadIdx.x & 31, w = threadIdx.x >> 5;
    if (lane == 0) red[w] = v;
    __syncthreads();
    float r = (threadIdx.x < 8) ? red[threadIdx.x] : 0.0f;
    if (threadIdx.x < 32) {
        #pragma unroll
        for (int o = 4; o; o >>= 1) r += __shfl_xor_sync(0xffffffffu, r, o);
        if (threadIdx.x == 0) red[0] = r;
    }
    __syncthreads();
    float out = red[0];
    __syncthreads();
    return out;
}

// ---------------------------------------------------------------------------
// LayerNorm -> hi/lo bf16
// ---------------------------------------------------------------------------
__global__ void ln_kernel(const float* __restrict__ text,
                          const float* __restrict__ gamma,
                          const float* __restrict__ beta) {
    int row = blockIdx.x;
    const float4* x = (const float4*)(text + (size_t)row * DIM);
    int tid = threadIdx.x;
    __shared__ float red[8];

    float4 v = x[tid];
    float s = v.x + v.y + v.z + v.w;
    float mu = blockReduceSum256(s, red) * (1.0f / DIM);
    float dx = v.x - mu, dy = v.y - mu, dz = v.z - mu, dw = v.w - mu;
    float ss = dx * dx + dy * dy + dz * dz + dw * dw;
    float var = blockReduceSum256(ss, red) * (1.0f / DIM);
    float inv = rsqrtf(var + EPS);
    float4 g = ((const float4*)gamma)[tid];
    float4 bt = ((const float4*)beta)[tid];
    float o[4];
    o[0] = dx * inv * g.x + bt.x;
    o[1] = dy * inv * g.y + bt.y;
    o[2] = dz * inv * g.z + bt.z;
    o[3] = dw * inv * g.w + bt.w;
    __nv_bfloat16 h[4], l[4];
    #pragma unroll
    for (int i = 0; i < 4; i++) split2(o[i], h[i], l[i]);
    size_t base = (size_t)row * DIM + 4 * tid;
    *(__nv_bfloat162*)(g_tn_hi + base)     = __nv_bfloat162(h[0], h[1]);
    *(__nv_bfloat162*)(g_tn_hi + base + 2) = __nv_bfloat162(h[2], h[3]);
    *(__nv_bfloat162*)(g_tn_lo + base)     = __nv_bfloat162(l[0], l[1]);
    *(__nv_bfloat162*)(g_tn_lo + base + 2) = __nv_bfloat162(l[2], l[3]);
}

// ---------------------------------------------------------------------------
// image fp32 -> hi/lo bf16 (elementwise)
// ---------------------------------------------------------------------------
__global__ void conv_img(const float* __restrict__ img) {
    size_t i = ((size_t)blockIdx.x * 256 + threadIdx.x) * 4;
    float4 v = *(const float4*)(img + i);
    __nv_bfloat16 h[4], l[4];
    split2(v.x, h[0], l[0]); split2(v.y, h[1], l[1]);
    split2(v.z, h[2], l[2]); split2(v.w, h[3], l[3]);
    *(__nv_bfloat162*)(g_img_hi + i)     = __nv_bfloat162(h[0], h[1]);
    *(__nv_bfloat162*)(g_img_hi + i + 2) = __nv_bfloat162(h[2], h[3]);
    *(__nv_bfloat162*)(g_img_lo + i)     = __nv_bfloat162(l[0], l[1]);
    *(__nv_bfloat162*)(g_img_lo + i + 2) = __nv_bfloat162(l[2], l[3]);
}

// ---------------------------------------------------------------------------
// W [K,N] fp32 -> W^T [N,K] hi/lo bf16 (tiled transpose)
// ---------------------------------------------------------------------------
__global__ void wtrans(const float* __restrict__ W,
                       __nv_bfloat16* __restrict__ Thi,
                       __nv_bfloat16* __restrict__ Tlo,
                       int Kd, int Nd) {
    __shared__ float t[32][33];
    int bx = blockIdx.x * 32;  // N offset
    int by = blockIdx.y * 32;  // K offset
    int x = threadIdx.x & 31, y4 = (threadIdx.x >> 5) * 4;
    #pragma unroll
    for (int i = 0; i < 4; i++)
        t[y4 + i][x] = W[(size_t)(by + y4 + i) * Nd + bx + x];
    __syncthreads();
    #pragma unroll
    for (int i = 0; i < 4; i++) {
        float v = t[x][y4 + i];
        __nv_bfloat16 h, l;
        split2(v, h, l);
        size_t o = (size_t)(bx + y4 + i) * Kd + by + x;
        Thi[o] = h;
        Tlo[o] = l;
    }
}

// ---------------------------------------------------------------------------
// bf16 split GEMM via mma.sync (HMMA):  C[M,N] = A[M,K] @ B^T  (B stored [N,K])
// Effective K' = 3K via [A_hi|A_hi|A_lo] . [B_hi|B_lo|B_hi]
// Tile 128x128, BK=64, 256 thr (8 warps, each 64x32), cp.async double buffer.
// MODE 0: full GEMM (kv)
// MODE 1: q — skip tiles with no segment rows (tt in [1..4])
// MODE 2: out — tiles with no segment rows filled from omean / zero
// ---------------------------------------------------------------------------
#define GBM 128
#define GBN 128
#define GBK 64
#define KTILES 48                     // 3*1024/64
#define ABYTES (GBM * GBK * 2)        // 16384
#define BBYTES (GBN * GBK * 2)        // 16384
#define SMEM_GEMM (2 * (ABYTES + BBYTES))   // 65536

template<int MODE>
__global__ __launch_bounds__(256, 2)
void gemm_hmma_split(const __nv_bfloat16* __restrict__ A_hi,
                     const __nv_bfloat16* __restrict__ A_lo,
                     const __nv_bfloat16* __restrict__ B_hi,
                     const __nv_bfloat16* __restrict__ B_lo,
                     float* __restrict__ C, int N) {
    extern __shared__ char smem[];
    const int K = 1024;
    uint32_t sb = smem_u32(smem);
    int tid = threadIdx.x;
    int lane = tid & 31, wid = tid >> 5;
    int row0 = blockIdx.y * GBM, col0 = blockIdx.x * GBN;

    if (MODE >= 1) {
        int tta = g_tt[row0], ttz = g_tt[row0 + GBM - 1];
        bool inactive = (tta > T_MEDIA) || (ttz == 0);
        if (MODE == 1 && inactive) return;
        if (MODE == 2 && inactive) {
            // fill: rows are either all tt>4 (omean) / all tt==0 (zero);
            // per-row select handles either case uniformly.
            int b = row0 >> 11;
            int cg = lane;                 // 32 col groups of 4
            int rs = tid >> 5;             // 8 row starters
            float4 ov = *(const float4*)(g_omean + b * DIM + col0 + 4 * cg);
            float4 zv = make_float4(0.f, 0.f, 0.f, 0.f);
            #pragma unroll 4
            for (int r = rs; r < GBM; r += 8) {
                int row = row0 + r;
                float4 val = (g_tt[row] == 0) ? zv : ov;
                *(float4*)(C + (size_t)row * N + col0 + 4 * cg) = val;
            }
            return;
        }
    }

    const uint32_t aoff[2] = {0u, (uint32_t)(ABYTES + BBYTES)};
    const uint32_t boff[2] = {(uint32_t)ABYTES, (uint32_t)(2 * ABYTES + BBYTES)};

    // loader indices: 1024 16B-chunks per tile, 4 per thread
    int lr = tid >> 3;            // 0..31
    int lc = tid & 7;             // 0..7 (16B chunk within 128B row)

    // compute indices
    int wm = wid >> 2, wn = wid & 3;
    int m_warp = wm * 64, n_warp = wn * 32;
    int a_row = lane & 15;
    int a_colb = (lane >> 4) * 8;            // k offset 0/8
    int b_row = (lane & 7) + 8 * ((lane >> 4) & 1);
    int b_colb = 8 * ((lane >> 3) & 1);

    float acc[4][4][4];
    #pragma unroll
    for (int i = 0; i < 4; i++)
        #pragma unroll
        for (int j = 0; j < 4; j++)
            #pragma unroll
            for (int q = 0; q < 4; q++) acc[i][j][q] = 0.0f;

    // ---- async load of one (A,B) k-chunk into buffer ----
    auto issue = [&](int kt) {
        int term = kt >> 4;
        int ks = (kt & 15) * GBK;
        int buf = kt & 1;
        const __nv_bfloat16* Ag = (term < 2) ? A_hi : A_lo;
        const __nv_bfloat16* Bg = (term == 1) ? B_lo : B_hi;
        #pragma unroll
        for (int j = 0; j < 4; j++) {
            int r = lr + 32 * j;
            uint32_t off = (uint32_t)(r * 128 + lc * 16);
            cp_async16(sb + aoff[buf] + sw128(off),
                       Ag + (size_t)(row0 + r) * K + ks + lc * 8);
        }
        #pragma unroll
        for (int j = 0; j < 4; j++) {
            int r = lr + 32 * j;
            uint32_t off = (uint32_t)(r * 128 + lc * 16);
            cp_async16(sb + boff[buf] + sw128(off),
                       Bg + (size_t)(col0 + r) * K + ks + lc * 8);
        }
        asm volatile("cp.async.commit_group;" ::: "memory");
    };

    issue(0);

    #pragma unroll 1
    for (int kt = 0; kt < KTILES; kt++) {
        int buf = kt & 1;
        if (kt + 1 < KTILES) {
            issue(kt + 1);
            asm volatile("cp.async.wait_group 1;" ::: "memory");
        } else {
            asm volatile("cp.async.wait_group 0;" ::: "memory");
        }
        __syncthreads();

        uint32_t ab = sb + aoff[buf], bb = sb + boff[buf];
        #pragma unroll
        for (int k16 = 0; k16 < 4; k16++) {
            uint32_t a_r[4][4], b_r[2][4];
            #pragma unroll
            for (int mf = 0; mf < 4; mf++) {
                uint32_t off = (uint32_t)((m_warp + mf * 16 + a_row) * 128 +
                                          (k16 * 16 + a_colb) * 2);
                ldsm4(a_r[mf], ab + sw128(off));
            }
            #pragma unroll
            for (int nf2 = 0; nf2 < 2; nf2++) {
                uint32_t off = (uint32_t)((n_warp + nf2 * 16 + b_row) * 128 +
                                          (k16 * 16 + b_colb) * 2);
                ldsm4(b_r[nf2], bb + sw128(off));
            }
            #pragma unroll
            for (int mf = 0; mf < 4; mf++)
                #pragma unroll
                for (int nf = 0; nf < 4; nf++) {
                    const uint32_t* b2 = &b_r[nf >> 1][(nf & 1) * 2];
                    mma16816(acc[mf][nf], a_r[mf], b2[0], b2[1]);
                }
        }
        __syncthreads();
    }

    // ---- epilogue ----
    int r_base = row0 + m_warp + (lane >> 2);
    int c_base = col0 + n_warp + 2 * (lane & 3);
    #pragma unroll
    for (int mf = 0; mf < 4; mf++)
        #pragma unroll
        for (int nf = 0; nf < 4; nf++) {
            float* p = C + (size_t)(r_base + mf * 16) * N + c_base + nf * 8;
            *(float2*)p = make_float2(acc[mf][nf][0], acc[mf][nf][1]);
            *(float2*)(p + (size_t)8 * N) = make_float2(acc[mf][nf][2], acc[mf][nf][3]);
        }
}

// ---------------------------------------------------------------------------
// v column partial sums + final mean (32 row-chunks for occupancy)
// ---------------------------------------------------------------------------
__global__ void vpart_kernel() {
    int c  = blockIdx.x * 256 + threadIdx.x;
    int ry = blockIdx.y;                    // 0..31 (32 rows each)
    int b  = blockIdx.z;
    const float* base = g_kv + ((size_t)(b * TM_TOT + ry * 32)) * (2 * DIM) + DIM + c;
    float s = 0.0f;
    #pragma unroll 8
    for (int j = 0; j < 32; j++) s += base[(size_t)j * (2 * DIM)];
    g_vpart[(b * 32 + ry) * DIM + c] = s;
}

__global__ void vmean_kernel() {
    int c = blockIdx.x * 256 + threadIdx.x;
    int b = blockIdx.y;
    float s = 0.0f;
    #pragma unroll
    for (int r = 0; r < 32; r++) s += g_vpart[(b * 32 + r) * DIM + c];
    g_vmean[b * DIM + c] = s * (1.0f / TM_TOT);
}

// ---------------------------------------------------------------------------
// omean[b] = vmean[b] @ Wo  (fp32 exact GEMV)
// ---------------------------------------------------------------------------
__global__ void omean_kernel(const float* __restrict__ Wo) {
    int n = blockIdx.x * 256 + threadIdx.x;
    int b = blockIdx.y;
    const float* vm = g_vmean + b * DIM;
    float acc = 0.0f;
    #pragma unroll 4
    for (int k = 0; k < DIM; k += 4) {
        float4 v = *(const float4*)(vm + k);
        acc += v.x * Wo[(size_t)k * DIM + n];
        acc += v.y * Wo[(size_t)(k + 1) * DIM + n];
        acc += v.z * Wo[(size_t)(k + 2) * DIM + n];
        acc += v.w * Wo[(size_t)(k + 3) * DIM + n];
    }
    g_omean[b * DIM + n] = acc;
}

// ---------------------------------------------------------------------------
// Attention dispatch -> writes hi/lo bf16 rows (A of the Wo GEMM).
// Rows belonging to pure-fill output tiles are skipped (never read).
// ---------------------------------------------------------------------------
__global__ __launch_bounds__(256)
void attn_kernel() {
    int bi = blockIdx.x;
    int b = bi >> 11;
    int i = bi & (NTXT - 1);
    int tid = threadIdx.x;
    int tt = g_tt[b * NTXT + i];
    __nv_bfloat16* oh = g_at_hi + (size_t)bi * DIM;
    __nv_bfloat16* ol = g_at_lo + (size_t)bi * DIM;

    if (tt == 0) {
        if (g_tt[bi | 127] == 0) return;    // whole tile pure-zero -> filled
        __nv_bfloat16 z = __float2bfloat16(0.0f);
        #pragma unroll
        for (int r = 0; r < 4; r++) { oh[tid + 256 * r] = z; ol[tid + 256 * r] = z; }
        return;
    }
    if (tt > T_MEDIA) {
        if (g_tt[bi & ~127] > T_MEDIA) return;  // whole tile pure-omean -> filled
        const float* vm = g_vmean + b * DIM;
        #pragma unroll
        for (int r = 0; r < 4; r++) {
            __nv_bfloat16 h, l;
            split2(vm[tid + 256 * r], h, l);
            oh[tid + 256 * r] = h; ol[tid + 256 * r] = l;
        }
        return;
    }

    __shared__ float qs[DIM];
    __shared__ float S[HEADS * M_MEDIA];
    int j0 = (tt - 1) * M_MEDIA;
    ((float4*)qs)[tid] = ((const float4*)(g_q + (size_t)bi * DIM))[tid];
    __syncthreads();

    const float scale = 0.125f;
    int h = tid >> 4, jj = tid & 15;
    #pragma unroll 2
    for (int jb = 0; jb < 16; jb++) {
        int j = jj * 16 + jb;
        const float* krow = g_kv + ((size_t)(b * TM_TOT + j0 + j)) * (2 * DIM) + h * DH;
        const float* qh = qs + h * DH;
        float s = 0.0f;
        #pragma unroll
        for (int d = 0; d < DH; d += 4) {
            float4 k4 = *(const float4*)(krow + d);
            float4 q4 = *(const float4*)(qh + d);
            s += q4.x * k4.x + q4.y * k4.y + q4.z * k4.z + q4.w * k4.w;
        }
        S[h * M_MEDIA + j] = s * scale;
    }
    __syncthreads();

    int w = tid >> 5, lane = tid & 31;
    for (int hh = 2 * w; hh < 2 * w + 2; hh++) {
        float vals[8];
        float m = -1e30f;
        #pragma unroll
        for (int k = 0; k < 8; k++) {
            vals[k] = S[hh * M_MEDIA + lane + 32 * k];
            m = fmaxf(m, vals[k]);
        }
        #pragma unroll
        for (int o = 16; o; o >>= 1) m = fmaxf(m, __shfl_xor_sync(0xffffffffu, m, o));
        float sum = 0.0f;
        #pragma unroll
        for (int k = 0; k < 8; k++) { vals[k] = __expf(vals[k] - m); sum += vals[k]; }
        #pragma unroll
        for (int o = 16; o; o >>= 1) sum += __shfl_xor_sync(0xffffffffu, sum, o);
        float inv = 1.0f / sum;
        #pragma unroll
        for (int k = 0; k < 8; k++) S[hh * M_MEDIA + lane + 32 * k] = vals[k] * inv;
    }
    __syncthreads();

    float acc[4] = {0.f, 0.f, 0.f, 0.f};
    const float* vbase = g_kv + ((size_t)(b * TM_TOT + j0)) * (2 * DIM) + DIM;
    #pragma unroll 4
    for (int j = 0; j < M_MEDIA; j++) {
        const float* vr = vbase + (size_t)j * (2 * DIM);
        #pragma unroll
        for (int r = 0; r < 4; r++) {
            int c = tid + 256 * r;
            acc[r] = fmaf(S[(c >> 6) * M_MEDIA + j], vr[c], acc[r]);
        }
    }
    #pragma unroll
    for (int r = 0; r < 4; r++) {
        __nv_bfloat16 hh, ll;
        split2(acc[r], hh, ll);
        oh[tid + 256 * r] = hh; ol[tid + 256 * r] = ll;
    }
}

// ---------------------------------------------------------------------------
// Launch
// ---------------------------------------------------------------------------
extern "C" void kernel_launch(void* const* d_in, const int* in_sizes, int n_in,
                              void* d_out, int out_size) {
    const float* text  = (const float*)d_in[0];
    const float* image = (const float*)d_in[1];
    const int*   loc   = (const int*)d_in[2];
    const float* Wq    = (const float*)d_in[3];
    const float* Wkv   = (const float*)d_in[4];
    const float* Wo    = (const float*)d_in[5];
    const float* gamma = (const float*)d_in[6];
    const float* beta  = (const float*)d_in[7];
    float* out = (float*)d_out;

    static int smem_set = 0;
    if (!smem_set) {
        cudaFuncSetAttribute(gemm_hmma_split<0>,
                             cudaFuncAttributeMaxDynamicSharedMemorySize, SMEM_GEMM);
        cudaFuncSetAttribute(gemm_hmma_split<1>,
                             cudaFuncAttributeMaxDynamicSharedMemorySize, SMEM_GEMM);
        cudaFuncSetAttribute(gemm_hmma_split<2>,
                             cudaFuncAttributeMaxDynamicSharedMemorySize, SMEM_GEMM);
        smem_set = 1;
    }

    __nv_bfloat16 *tn_hi, *tn_lo, *img_hi, *img_lo, *at_hi, *at_lo;
    __nv_bfloat16 *wq_hi, *wq_lo, *wkv_hi, *wkv_lo, *wo_hi, *wo_lo;
    float *p_q, *p_kv;
    cudaGetSymbolAddress((void**)&tn_hi,  g_tn_hi);
    cudaGetSymbolAddress((void**)&tn_lo,  g_tn_lo);
    cudaGetSymbolAddress((void**)&img_hi, g_img_hi);
    cudaGetSymbolAddress((void**)&img_lo, g_img_lo);
    cudaGetSymbolAddress((void**)&at_hi,  g_at_hi);
    cudaGetSymbolAddress((void**)&at_lo,  g_at_lo);
    cudaGetSymbolAddress((void**)&wq_hi,  g_Wq_hi);
    cudaGetSymbolAddress((void**)&wq_lo,  g_Wq_lo);
    cudaGetSymbolAddress((void**)&wkv_hi, g_Wkv_hi);
    cudaGetSymbolAddress((void**)&wkv_lo, g_Wkv_lo);
    cudaGetSymbolAddress((void**)&wo_hi,  g_Wo_hi);
    cudaGetSymbolAddress((void**)&wo_lo,  g_Wo_lo);
    cudaGetSymbolAddress((void**)&p_q,    g_q);
    cudaGetSymbolAddress((void**)&p_kv,   g_kv);

    // scan + LN + conversions
    scan_kernel<<<BATCH, 1024>>>(loc);
    ln_kernel<<<MQ, 256>>>(text, gamma, beta);
    conv_img<<<(MKV * DIM) / (256 * 4), 256>>>(image);
    wtrans<<<dim3(2 * DIM / 32, DIM / 32), 256>>>(Wkv, wkv_hi, wkv_lo, DIM, 2 * DIM);
    wtrans<<<dim3(DIM / 32, DIM / 32), 256>>>(Wq, wq_hi, wq_lo, DIM, DIM);
    wtrans<<<dim3(DIM / 32, DIM / 32), 256>>>(Wo, wo_hi, wo_lo, DIM, DIM);

    // kv = image @ Wkv   (2048 x 2048) — full
    gemm_hmma_split<0><<<dim3(2 * DIM / GBN, MKV / GBM), 256, SMEM_GEMM>>>(
        img_hi, img_lo, wkv_hi, wkv_lo, p_kv, 2 * DIM);

    vpart_kernel<<<dim3(DIM / 256, 32, BATCH), 256>>>();
    vmean_kernel<<<dim3(DIM / 256, BATCH), 256>>>();
    omean_kernel<<<dim3(DIM / 256, BATCH), 256>>>(Wo);

    // q = tn @ Wq        (4096 x 1024) — only tiles containing segment rows
    gemm_hmma_split<1><<<dim3(DIM / GBN, MQ / GBM), 256, SMEM_GEMM>>>(
        tn_hi, tn_lo, wq_hi, wq_lo, p_q, DIM);

    attn_kernel<<<MQ, 256>>>();

    // out = attn @ Wo    (4096 x 1024) — pure tiles broadcast omean/zero
    gemm_hmma_split<2><<<dim3(DIM / GBN, MQ / GBM), 256, SMEM_GEMM>>>(
        at_hi, at_lo, wo_hi, wo_lo, out, DIM);
}

// round 6
// speedup vs baseline: 2.6718x; 1.0180x over previous
#include <cuda_runtime.h>
#include <cuda_bf16.h>
#include <math.h>
#include <stdint.h>

// Problem constants
#define BATCH   2
#define NTXT    2048
#define T_MEDIA 4
#define M_MEDIA 256
#define TM_TOT  1024
#define DIM     1024
#define HEADS   16
#define DH      64
#define EPS     1e-5f

#define MQ  (BATCH * NTXT)     // 4096
#define MKV (BATCH * TM_TOT)   // 2048

// ---------------------------------------------------------------------------
// Scratch (device globals; no allocations allowed)
// ---------------------------------------------------------------------------
__device__ __nv_bfloat16 g_img_hi[MKV * DIM];
__device__ __nv_bfloat16 g_img_lo[MKV * DIM];
__device__ __nv_bfloat16 g_Wkv_hi[2 * DIM * DIM];
__device__ __nv_bfloat16 g_Wkv_lo[2 * DIM * DIM];

__device__ float g_kv   [MKV * 2 * DIM];           // k | v (fp32)
__device__ float g_vpart[BATCH * 32 * DIM];
__device__ float g_vmean[BATCH * DIM];
__device__ float g_omean[BATCH * DIM];             // vmean @ Wo (fp32)
__device__ int   g_tt   [BATCH * NTXT];            // txt_time
__device__ int   g_act  [MQ];                      // active rows (tt in [1..4])
__device__ int   g_nact;
__device__ float g_qact [MQ * DIM];                // q rows for active queries
__device__ float g_oact [MQ * DIM];                // attention out for active queries

// ---------------------------------------------------------------------------
// PTX helpers (sm_80-baseline only; NO tcgen05 — ptxas target lacks 'a')
// ---------------------------------------------------------------------------
__device__ __forceinline__ uint32_t smem_u32(const void* p) {
    uint32_t a;
    asm("{ .reg .u64 t; cvta.to.shared.u64 t, %1; cvt.u32.u64 %0, t; }" : "=r"(a) : "l"(p));
    return a;
}
__device__ __forceinline__ void cp_async16(uint32_t dst, const void* src) {
    asm volatile("cp.async.cg.shared.global [%0], [%1], 16;\n" :: "r"(dst), "l"(src));
}
__device__ __forceinline__ void ldsm4(uint32_t* r, uint32_t addr) {
    asm volatile("ldmatrix.sync.aligned.m8n8.x4.shared.b16 {%0,%1,%2,%3}, [%4];"
                 : "=r"(r[0]), "=r"(r[1]), "=r"(r[2]), "=r"(r[3]) : "r"(addr));
}
__device__ __forceinline__ void mma16816(float* c, const uint32_t* a,
                                         uint32_t b0, uint32_t b1) {
    asm volatile(
        "mma.sync.aligned.m16n8k16.row.col.f32.bf16.bf16.f32 "
        "{%0,%1,%2,%3}, {%4,%5,%6,%7}, {%8,%9}, {%0,%1,%2,%3};"
        : "+f"(c[0]), "+f"(c[1]), "+f"(c[2]), "+f"(c[3])
        : "r"(a[0]), "r"(a[1]), "r"(a[2]), "r"(a[3]), "r"(b0), "r"(b1));
}
__device__ __forceinline__ uint32_t sw128(uint32_t off) {
    return off ^ ((off >> 3) & 0x70);
}
__device__ __forceinline__ void split2(float v, __nv_bfloat16& h, __nv_bfloat16& l) {
    h = __float2bfloat16(v);
    l = __float2bfloat16(v - __bfloat162float(h));
}

// ---------------------------------------------------------------------------
// Inclusive scan of locations -> txt_time.  One block of 1024 per batch.
// Also resets the active-row counter for this replay.
// ---------------------------------------------------------------------------
__global__ void scan_kernel(const int* __restrict__ loc) {
    int b = blockIdx.x;
    int tid = threadIdx.x;
    if (b == 0 && tid == 0) g_nact = 0;
    __shared__ int s[1024];
    const int* L = loc + b * NTXT;
    int a0 = L[2 * tid];
    int a1 = L[2 * tid + 1];
    int v0 = a0, v1 = a0 + a1;
    s[tid] = v1;
    __syncthreads();
    for (int off = 1; off < 1024; off <<= 1) {
        int t = (tid >= off) ? s[tid - off] : 0;
        __syncthreads();
        s[tid] += t;
        __syncthreads();
    }
    int excl = s[tid] - v1;
    g_tt[b * NTXT + 2 * tid]     = excl + v0;
    g_tt[b * NTXT + 2 * tid + 1] = excl + v1;
}

// ---------------------------------------------------------------------------
// Build list of active rows (tt in [1..T_MEDIA])
// ---------------------------------------------------------------------------
__global__ void compact_kernel() {
    int row = blockIdx.x * 1024 + threadIdx.x;
    int tt = g_tt[row];
    if (tt >= 1 && tt <= T_MEDIA) {
        int slot = atomicAdd(&g_nact, 1);
        g_act[slot] = row;
    }
}

// ---------------------------------------------------------------------------
// Block reduce helper (256 threads)
// ---------------------------------------------------------------------------
__device__ __forceinline__ float blockReduceSum256(float v, float* red) {
    #pragma unroll
    for (int o = 16; o; o >>= 1) v += __shfl_xor_sync(0xffffffffu, v, o);
    int lane = threadIdx.x & 31, w = threadIdx.x >> 5;
    if (lane == 0) red[w] = v;
    __syncthreads();
    float r = (threadIdx.x < 8) ? red[threadIdx.x] : 0.0f;
    if (threadIdx.x < 32) {
        #pragma unroll
        for (int o = 4; o; o >>= 1) r += __shfl_xor_sync(0xffffffffu, r, o);
        if (threadIdx.x == 0) red[0] = r;
    }
    __syncthreads();
    float out = red[0];
    __syncthreads();
    return out;
}

// ---------------------------------------------------------------------------
// image fp32 -> hi/lo bf16 (elementwise)
// ---------------------------------------------------------------------------
__global__ void conv_img(const float* __restrict__ img) {
    size_t i = ((size_t)blockIdx.x * 256 + threadIdx.x) * 4;
    float4 v = *(const float4*)(img + i);
    __nv_bfloat16 h[4], l[4];
    split2(v.x, h[0], l[0]); split2(v.y, h[1], l[1]);
    split2(v.z, h[2], l[2]); split2(v.w, h[3], l[3]);
    *(__nv_bfloat162*)(g_img_hi + i)     = __nv_bfloat162(h[0], h[1]);
    *(__nv_bfloat162*)(g_img_hi + i + 2) = __nv_bfloat162(h[2], h[3]);
    *(__nv_bfloat162*)(g_img_lo + i)     = __nv_bfloat162(l[0], l[1]);
    *(__nv_bfloat162*)(g_img_lo + i + 2) = __nv_bfloat162(l[2], l[3]);
}

// ---------------------------------------------------------------------------
// W [K,N] fp32 -> W^T [N,K] hi/lo bf16 (tiled transpose) — Wkv only
// ---------------------------------------------------------------------------
__global__ void wtrans(const float* __restrict__ W,
                       __nv_bfloat16* __restrict__ Thi,
                       __nv_bfloat16* __restrict__ Tlo,
                       int Kd, int Nd) {
    __shared__ float t[32][33];
    int bx = blockIdx.x * 32;  // N offset
    int by = blockIdx.y * 32;  // K offset
    int x = threadIdx.x & 31, y4 = (threadIdx.x >> 5) * 4;
    #pragma unroll
    for (int i = 0; i < 4; i++)
        t[y4 + i][x] = W[(size_t)(by + y4 + i) * Nd + bx + x];
    __syncthreads();
    #pragma unroll
    for (int i = 0; i < 4; i++) {
        float v = t[x][y4 + i];
        __nv_bfloat16 h, l;
        split2(v, h, l);
        size_t o = (size_t)(bx + y4 + i) * Kd + by + x;
        Thi[o] = h;
        Tlo[o] = l;
    }
}

// ---------------------------------------------------------------------------
// bf16 split GEMM via mma.sync (HMMA):  C[M,N] = A[M,K] @ B^T  (B stored [N,K])
// Effective K' = 3K via [A_hi|A_hi|A_lo] . [B_hi|B_lo|B_hi]
// Tile 128x128, BK=64, 256 thr (8 warps, each 64x32), cp.async double buffer.
// ---------------------------------------------------------------------------
#define GBM 128
#define GBN 128
#define GBK 64
#define KTILES 48                     // 3*1024/64
#define ABYTES (GBM * GBK * 2)        // 16384
#define BBYTES (GBN * GBK * 2)        // 16384
#define SMEM_GEMM (2 * (ABYTES + BBYTES))   // 65536

__global__ __launch_bounds__(256, 2)
void gemm_hmma_split(const __nv_bfloat16* __restrict__ A_hi,
                     const __nv_bfloat16* __restrict__ A_lo,
                     const __nv_bfloat16* __restrict__ B_hi,
                     const __nv_bfloat16* __restrict__ B_lo,
                     float* __restrict__ C, int N) {
    extern __shared__ char smem[];
    const int K = 1024;
    uint32_t sb = smem_u32(smem);
    int tid = threadIdx.x;
    int lane = tid & 31, wid = tid >> 5;
    int row0 = blockIdx.y * GBM, col0 = blockIdx.x * GBN;

    const uint32_t aoff[2] = {0u, (uint32_t)(ABYTES + BBYTES)};
    const uint32_t boff[2] = {(uint32_t)ABYTES, (uint32_t)(2 * ABYTES + BBYTES)};

    int lr = tid >> 3;            // 0..31
    int lc = tid & 7;             // 0..7 (16B chunk within 128B row)

    int wm = wid >> 2, wn = wid & 3;
    int m_warp = wm * 64, n_warp = wn * 32;
    int a_row = lane & 15;
    int a_colb = (lane >> 4) * 8;
    int b_row = (lane & 7) + 8 * ((lane >> 4) & 1);
    int b_colb = 8 * ((lane >> 3) & 1);

    float acc[4][4][4];
    #pragma unroll
    for (int i = 0; i < 4; i++)
        #pragma unroll
        for (int j = 0; j < 4; j++)
            #pragma unroll
            for (int q = 0; q < 4; q++) acc[i][j][q] = 0.0f;

    auto issue = [&](int kt) {
        int term = kt >> 4;
        int ks = (kt & 15) * GBK;
        int buf = kt & 1;
        const __nv_bfloat16* Ag = (term < 2) ? A_hi : A_lo;
        const __nv_bfloat16* Bg = (term == 1) ? B_lo : B_hi;
        #pragma unroll
        for (int j = 0; j < 4; j++) {
            int r = lr + 32 * j;
            uint32_t off = (uint32_t)(r * 128 + lc * 16);
            cp_async16(sb + aoff[buf] + sw128(off),
                       Ag + (size_t)(row0 + r) * K + ks + lc * 8);
        }
        #pragma unroll
        for (int j = 0; j < 4; j++) {
            int r = lr + 32 * j;
            uint32_t off = (uint32_t)(r * 128 + lc * 16);
            cp_async16(sb + boff[buf] + sw128(off),
                       Bg + (size_t)(col0 + r) * K + ks + lc * 8);
        }
        asm volatile("cp.async.commit_group;" ::: "memory");
    };

    issue(0);

    #pragma unroll 1
    for (int kt = 0; kt < KTILES; kt++) {
        int buf = kt & 1;
        if (kt + 1 < KTILES) {
            issue(kt + 1);
            asm volatile("cp.async.wait_group 1;" ::: "memory");
        } else {
            asm volatile("cp.async.wait_group 0;" ::: "memory");
        }
        __syncthreads();

        uint32_t ab = sb + aoff[buf], bb = sb + boff[buf];
        #pragma unroll
        for (int k16 = 0; k16 < 4; k16++) {
            uint32_t a_r[4][4], b_r[2][4];
            #pragma unroll
            for (int mf = 0; mf < 4; mf++) {
                uint32_t off = (uint32_t)((m_warp + mf * 16 + a_row) * 128 +
                                          (k16 * 16 + a_colb) * 2);
                ldsm4(a_r[mf], ab + sw128(off));
            }
            #pragma unroll
            for (int nf2 = 0; nf2 < 2; nf2++) {
                uint32_t off = (uint32_t)((n_warp + nf2 * 16 + b_row) * 128 +
                                          (k16 * 16 + b_colb) * 2);
                ldsm4(b_r[nf2], bb + sw128(off));
            }
            #pragma unroll
            for (int mf = 0; mf < 4; mf++)
                #pragma unroll
                for (int nf = 0; nf < 4; nf++) {
                    const uint32_t* b2 = &b_r[nf >> 1][(nf & 1) * 2];
                    mma16816(acc[mf][nf], a_r[mf], b2[0], b2[1]);
                }
        }
        __syncthreads();
    }

    int r_base = row0 + m_warp + (lane >> 2);
    int c_base = col0 + n_warp + 2 * (lane & 3);
    #pragma unroll
    for (int mf = 0; mf < 4; mf++)
        #pragma unroll
        for (int nf = 0; nf < 4; nf++) {
            float* p = C + (size_t)(r_base + mf * 16) * N + c_base + nf * 8;
            *(float2*)p = make_float2(acc[mf][nf][0], acc[mf][nf][1]);
            *(float2*)(p + (size_t)8 * N) = make_float2(acc[mf][nf][2], acc[mf][nf][3]);
        }
}

// ---------------------------------------------------------------------------
// v column partial sums + final mean + omean = vmean @ Wo (fp32 exact)
// ---------------------------------------------------------------------------
__global__ void vpart_kernel() {
    int c  = blockIdx.x * 256 + threadIdx.x;
    int ry = blockIdx.y;                    // 0..31
    int b  = blockIdx.z;
    const float* base = g_kv + ((size_t)(b * TM_TOT + ry * 32)) * (2 * DIM) + DIM + c;
    float s = 0.0f;
    #pragma unroll 8
    for (int j = 0; j < 32; j++) s += base[(size_t)j * (2 * DIM)];
    g_vpart[(b * 32 + ry) * DIM + c] = s;
}

__global__ void vmean_kernel() {
    int c = blockIdx.x * 256 + threadIdx.x;
    int b = blockIdx.y;
    float s = 0.0f;
    #pragma unroll
    for (int r = 0; r < 32; r++) s += g_vpart[(b * 32 + r) * DIM + c];
    g_vmean[b * DIM + c] = s * (1.0f / TM_TOT);
}

__global__ void omean_kernel(const float* __restrict__ Wo) {
    int n = blockIdx.x * 256 + threadIdx.x;
    int b = blockIdx.y;
    const float* vm = g_vmean + b * DIM;
    float acc = 0.0f;
    #pragma unroll 4
    for (int k = 0; k < DIM; k += 4) {
        float4 v = *(const float4*)(vm + k);
        acc += v.x * Wo[(size_t)k * DIM + n];
        acc += v.y * Wo[(size_t)(k + 1) * DIM + n];
        acc += v.z * Wo[(size_t)(k + 2) * DIM + n];
        acc += v.w * Wo[(size_t)(k + 3) * DIM + n];
    }
    g_omean[b * DIM + n] = acc;
}

// ---------------------------------------------------------------------------
// Fused LayerNorm + q GEMV for active rows only (fp32, exact).
// grid (DIM/256, 64); block handles (col chunk, slot stride).
// ---------------------------------------------------------------------------
__global__ __launch_bounds__(256)
void qact_kernel(const float* __restrict__ text,
                 const float* __restrict__ gamma,
                 const float* __restrict__ beta,
                 const float* __restrict__ Wq) {
    __shared__ float srow[DIM];
    __shared__ float red[8];
    int tid = threadIdx.x;
    int n = blockIdx.x * 256 + tid;
    int nact = g_nact;
    for (int s = blockIdx.y; s < nact; s += gridDim.y) {
        int row = g_act[s];
        // LayerNorm of text row (recomputed per col-chunk; 4 KB read, trivial)
        float4 v = ((const float4*)(text + (size_t)row * DIM))[tid];
        float sm = v.x + v.y + v.z + v.w;
        float mu = blockReduceSum256(sm, red) * (1.0f / DIM);
        float dx = v.x - mu, dy = v.y - mu, dz = v.z - mu, dw = v.w - mu;
        float ss = dx * dx + dy * dy + dz * dz + dw * dw;
        float var = blockReduceSum256(ss, red) * (1.0f / DIM);
        float inv = rsqrtf(var + EPS);
        float4 g = ((const float4*)gamma)[tid];
        float4 bt = ((const float4*)beta)[tid];
        srow[4 * tid + 0] = dx * inv * g.x + bt.x;
        srow[4 * tid + 1] = dy * inv * g.y + bt.y;
        srow[4 * tid + 2] = dz * inv * g.z + bt.z;
        srow[4 * tid + 3] = dw * inv * g.w + bt.w;
        __syncthreads();
        // GEMV: q[n] = sum_k srow[k] * Wq[k, n]
        float acc = 0.0f;
        #pragma unroll 8
        for (int k = 0; k < DIM; k++)
            acc = fmaf(srow[k], Wq[(size_t)k * DIM + n], acc);
        g_qact[(size_t)s * DIM + n] = acc;
        __syncthreads();
    }
}

// ---------------------------------------------------------------------------
// Segment attention for active rows -> g_oact (fp32). grid 64, slot stride.
// ---------------------------------------------------------------------------
__global__ __launch_bounds__(256)
void attn_act_kernel() {
    __shared__ float qs[DIM];
    __shared__ float S[HEADS * M_MEDIA];
    int tid = threadIdx.x;
    int nact = g_nact;
    for (int s = blockIdx.x; s < nact; s += gridDim.x) {
        int row = g_act[s];
        int b = row >> 11;
        int tt = g_tt[row];
        int j0 = (tt - 1) * M_MEDIA;
        ((float4*)qs)[tid] = ((const float4*)(g_qact + (size_t)s * DIM))[tid];
        __syncthreads();

        const float scale = 0.125f;
        int h = tid >> 4, jj = tid & 15;
        #pragma unroll 2
        for (int jb = 0; jb < 16; jb++) {
            int j = jj * 16 + jb;
            const float* krow = g_kv + ((size_t)(b * TM_TOT + j0 + j)) * (2 * DIM) + h * DH;
            const float* qh = qs + h * DH;
            float sm = 0.0f;
            #pragma unroll
            for (int d = 0; d < DH; d += 4) {
                float4 k4 = *(const float4*)(krow + d);
                float4 q4 = *(const float4*)(qh + d);
                sm += q4.x * k4.x + q4.y * k4.y + q4.z * k4.z + q4.w * k4.w;
            }
            S[h * M_MEDIA + j] = sm * scale;
        }
        __syncthreads();

        int w = tid >> 5, lane = tid & 31;
        for (int hh = 2 * w; hh < 2 * w + 2; hh++) {
            float vals[8];
            float m = -1e30f;
            #pragma unroll
            for (int k = 0; k < 8; k++) {
                vals[k] = S[hh * M_MEDIA + lane + 32 * k];
                m = fmaxf(m, vals[k]);
            }
            #pragma unroll
            for (int o = 16; o; o >>= 1) m = fmaxf(m, __shfl_xor_sync(0xffffffffu, m, o));
            float sum = 0.0f;
            #pragma unroll
            for (int k = 0; k < 8; k++) { vals[k] = __expf(vals[k] - m); sum += vals[k]; }
            #pragma unroll
            for (int o = 16; o; o >>= 1) sum += __shfl_xor_sync(0xffffffffu, sum, o);
            float inv = 1.0f / sum;
            #pragma unroll
            for (int k = 0; k < 8; k++) S[hh * M_MEDIA + lane + 32 * k] = vals[k] * inv;
        }
        __syncthreads();

        float acc[4] = {0.f, 0.f, 0.f, 0.f};
        const float* vbase = g_kv + ((size_t)(b * TM_TOT + j0)) * (2 * DIM) + DIM;
        #pragma unroll 4
        for (int j = 0; j < M_MEDIA; j++) {
            const float* vr = vbase + (size_t)j * (2 * DIM);
            #pragma unroll
            for (int r = 0; r < 4; r++) {
                int c = tid + 256 * r;
                acc[r] = fmaf(S[(c >> 6) * M_MEDIA + j], vr[c], acc[r]);
            }
        }
        float* orow = g_oact + (size_t)s * DIM;
        #pragma unroll
        for (int r = 0; r < 4; r++) orow[tid + 256 * r] = acc[r];
        __syncthreads();
    }
}

// ---------------------------------------------------------------------------
// Fill output: tt==0 -> 0, tt>4 -> omean, active -> skip (out_act writes)
// ---------------------------------------------------------------------------
__global__ void fill_kernel(float* __restrict__ out) {
    int row = blockIdx.x;
    int tt = g_tt[row];
    if (tt >= 1 && tt <= T_MEDIA) return;
    int tid = threadIdx.x;
    int b = row >> 11;
    float4 val = (tt == 0) ? make_float4(0.f, 0.f, 0.f, 0.f)
                           : ((const float4*)(g_omean + b * DIM))[tid];
    ((float4*)(out + (size_t)row * DIM))[tid] = val;
}

// ---------------------------------------------------------------------------
// out GEMV for active rows: out[row] = oact[s] @ Wo (fp32 exact)
// ---------------------------------------------------------------------------
__global__ __launch_bounds__(256)
void out_act_kernel(const float* __restrict__ Wo, float* __restrict__ out) {
    __shared__ float srow[DIM];
    int tid = threadIdx.x;
    int n = blockIdx.x * 256 + tid;
    int nact = g_nact;
    for (int s = blockIdx.y; s < nact; s += gridDim.y) {
        int row = g_act[s];
        ((float4*)srow)[tid] = ((const float4*)(g_oact + (size_t)s * DIM))[tid];
        __syncthreads();
        float acc = 0.0f;
        #pragma unroll 8
        for (int k = 0; k < DIM; k++)
            acc = fmaf(srow[k], Wo[(size_t)k * DIM + n], acc);
        out[(size_t)row * DIM + n] = acc;
        __syncthreads();
    }
}

// ---------------------------------------------------------------------------
// Launch
// ---------------------------------------------------------------------------
extern "C" void kernel_launch(void* const* d_in, const int* in_sizes, int n_in,
                              void* d_out, int out_size) {
    const float* text  = (const float*)d_in[0];
    const float* image = (const float*)d_in[1];
    const int*   loc   = (const int*)d_in[2];
    const float* Wq    = (const float*)d_in[3];
    const float* Wkv   = (const float*)d_in[4];
    const float* Wo    = (const float*)d_in[5];
    const float* gamma = (const float*)d_in[6];
    const float* beta  = (const float*)d_in[7];
    float* out = (float*)d_out;

    static int smem_set = 0;
    if (!smem_set) {
        cudaFuncSetAttribute(gemm_hmma_split,
                             cudaFuncAttributeMaxDynamicSharedMemorySize, SMEM_GEMM);
        smem_set = 1;
    }

    __nv_bfloat16 *img_hi, *img_lo, *wkv_hi, *wkv_lo;
    float *p_kv;
    cudaGetSymbolAddress((void**)&img_hi, g_img_hi);
    cudaGetSymbolAddress((void**)&img_lo, g_img_lo);
    cudaGetSymbolAddress((void**)&wkv_hi, g_Wkv_hi);
    cudaGetSymbolAddress((void**)&wkv_lo, g_Wkv_lo);
    cudaGetSymbolAddress((void**)&p_kv,   g_kv);

    // scan (resets g_nact) + compact + conversions
    scan_kernel<<<BATCH, 1024>>>(loc);
    compact_kernel<<<MQ / 1024, 1024>>>();
    conv_img<<<(MKV * DIM) / (256 * 4), 256>>>(image);
    wtrans<<<dim3(2 * DIM / 32, DIM / 32), 256>>>(Wkv, wkv_hi, wkv_lo, DIM, 2 * DIM);

    // kv = image @ Wkv   (2048 x 2048) — the only full GEMM
    gemm_hmma_split<<<dim3(2 * DIM / GBN, MKV / GBM), 256, SMEM_GEMM>>>(
        img_hi, img_lo, wkv_hi, wkv_lo, p_kv, 2 * DIM);

    // v statistics + mean-output row
    vpart_kernel<<<dim3(DIM / 256, 32, BATCH), 256>>>();
    vmean_kernel<<<dim3(DIM / 256, BATCH), 256>>>();
    omean_kernel<<<dim3(DIM / 256, BATCH), 256>>>(Wo);

    // active-row pipeline (LN + q GEMV -> attention -> out GEMV), all fp32
    qact_kernel<<<dim3(DIM / 256, 64), 256>>>(text, gamma, beta, Wq);
    attn_act_kernel<<<64, 256>>>();
    fill_kernel<<<MQ, 256>>>(out);
    out_act_kernel<<<dim3(DIM / 256, 64), 256>>>(Wo, out);
}